// round 3
// baseline (speedup 1.0000x reference)
#include <cuda_runtime.h>
#include <math.h>

#define B_   128
#define T_   512
#define H_   512
#define G_   2048
#define DIN_ 8
#define HOR_ 64
#define MQ_  5
#define DFF_ 7
#define NBLK 128

// ---------------- scratch (device globals; no allocations) ----------------
__device__ float g_h0seq[2][T_][B_][H_];     // layer-0 hidden sequence (both dirs)
__device__ float g_gates1[2][T_][B_][G_];    // precomputed layer-1 input gates
__device__ float g_c[2][2][B_][H_];          // final cell states [layer][dir]
__device__ float g_h1buf[2][2][B_][H_];      // layer-1 h ping-pong [pp][dir]
__device__ float g_dec_h0[2][B_][H_];
__device__ float g_dec_c0[B_][H_];
__device__ float g_dec_h1[2][B_][H_];
__device__ float g_dec_c1[B_][H_];
__device__ float g_decx[B_][DIN_];           // decoder input vector [y_fb, fut]
__device__ unsigned g_bar_cnt;
__device__ unsigned g_bar_gen;

// ---------------- software grid barrier (all NBLK blocks co-resident) ------
__device__ __forceinline__ void grid_barrier()
{
    __syncthreads();
    if (threadIdx.x == 0) {
        volatile unsigned* genp = &g_bar_gen;
        unsigned gen = *genp;
        __threadfence();                       // release prior writes
        if (atomicAdd(&g_bar_cnt, 1u) == NBLK - 1u) {
            g_bar_cnt = 0u;
            __threadfence();
            *genp = gen + 1u;
        } else {
            while (*genp == gen) { }
        }
        __threadfence();                       // acquire
    }
    __syncthreads();
}

// ---------------- fast transcendentals ----------------
__device__ __forceinline__ float sigm_(float x) {
    return __fdividef(1.f, 1.f + __expf(-x));
}
__device__ __forceinline__ float tanh_(float x) {
    return __fdividef(2.f, 1.f + __expf(-2.f * x)) - 1.f;
}

// ---------------- tiled GEMM segment accumulate ----------------
// Block tile: BT batch rows x 128 gate-cols (4 gate types x 32 hidden j).
// 256 threads: tx = j-lane (0..31), ty = batch group (0..7), NB = BT/8 rows each.
// a_s is transposed [kk][batch] so the batch fetch is one vector LDS.
template<int BT>
__device__ __forceinline__ void seg_accum(
    float (*a_s)[BT + 4], float (*w_s)[33],
    const float* __restrict__ xp, int xs, int use_ldcg,
    const float* __restrict__ wp, int ws, int K,
    int b0, int j0, float acc[BT / 8][4])
{
    const int tid = threadIdx.x, tx = tid & 31, ty = tid >> 5;
    constexpr int NB = BT / 8;
    for (int k0 = 0; k0 < K; k0 += 32) {
        __syncthreads();
        #pragma unroll
        for (int i = 0; i < (BT * 32) / 256; ++i) {          // a tile BTx32 -> [kk][r]
            int e = tid + i * 256;
            int r = e >> 5, kk = e & 31, kg = k0 + kk;
            float v = 0.f;
            if (kg < K) {
                const float* p = xp + (long)(b0 + r) * xs + kg;
                v = use_ldcg ? __ldcg(p) : __ldg(p);
            }
            a_s[kk][r] = v;
        }
        #pragma unroll
        for (int i = 0; i < 16; ++i) {                        // w tile 128x32 -> [c][kk]
            int e = tid + i * 256;
            int c = e >> 5, kk = e & 31, kg = k0 + kk;
            float v = 0.f;
            if (kg < K) {
                int gc = j0 + (c >> 5) * 512 + (c & 31);
                v = __ldg(wp + (long)gc * ws + kg);
            }
            w_s[c][kk] = v;
        }
        __syncthreads();
        #pragma unroll
        for (int kk = 0; kk < 32; ++kk) {
            float av[NB];
            if constexpr (NB == 4) {
                float4 a4 = *reinterpret_cast<const float4*>(&a_s[kk][ty * 4]);
                av[0] = a4.x; av[1] = a4.y; av[2] = a4.z; av[3] = a4.w;
            } else {
                float2 a2 = *reinterpret_cast<const float2*>(&a_s[kk][ty * 2]);
                av[0] = a2.x; av[1] = a2.y;
            }
            #pragma unroll
            for (int gi = 0; gi < 4; ++gi) {
                float wv = w_s[gi * 32 + tx][kk];
                #pragma unroll
                for (int bi = 0; bi < NB; ++bi)
                    acc[bi][gi] = fmaf(av[bi], wv, acc[bi][gi]);
            }
        }
    }
}

// ---------------- encoder layer 0: persistent, 512 steps, both dirs --------
__global__ __launch_bounds__(256, 1) void enc_l0_persist(
    const float* __restrict__ X, const float* __restrict__ w_ih,
    const float* __restrict__ w_hh, const float* __restrict__ bias)
{
    __shared__ float a_s[32][36];
    __shared__ float w_s[128][33];
    const int bid = blockIdx.x;
    const int dir = bid >> 6, rr = bid & 63;
    const int b0 = (rr >> 4) * 32, j0 = (rr & 15) * 32;
    const int tx = threadIdx.x & 31, ty = threadIdx.x >> 5;
    const int j = j0 + tx;
    const float* bs = bias + dir * G_;
    const float bI = __ldg(bs + j),        bF = __ldg(bs + 512 + j),
                bG = __ldg(bs + 1024 + j), bO = __ldg(bs + 1536 + j);
    const float* wih = w_ih + (long)dir * G_ * DIN_;
    const float* whh = w_hh + (long)dir * G_ * H_;
    float cacc[4] = {0.f, 0.f, 0.f, 0.f};

    for (int s = 0; s < T_; ++s) {
        const int t = dir ? (T_ - 1 - s) : s;
        float acc[4][4] = {};
        seg_accum<32>(a_s, w_s, X + t * DIN_, T_ * DIN_, 0, wih, DIN_, DIN_, b0, j0, acc);
        if (s > 0) {
            const int tp = dir ? t + 1 : t - 1;
            seg_accum<32>(a_s, w_s, &g_h0seq[dir][tp][0][0], H_, 1, whh, H_, H_, b0, j0, acc);
        }
        #pragma unroll
        for (int bi = 0; bi < 4; ++bi) {
            float i_ = sigm_(acc[bi][0] + bI);
            float f_ = sigm_(acc[bi][1] + bF);
            float g_ = tanh_(acc[bi][2] + bG);
            float o_ = sigm_(acc[bi][3] + bO);
            float c  = f_ * cacc[bi] + i_ * g_;
            cacc[bi] = c;
            g_h0seq[dir][t][b0 + ty * 4 + bi][j] = o_ * tanh_(c);
        }
        grid_barrier();
    }
    #pragma unroll
    for (int bi = 0; bi < 4; ++bi)
        g_c[0][dir][b0 + ty * 4 + bi][j] = cacc[bi];
}

// ---------------- layer-1 input gates: one big batched GEMM ----------------
__global__ __launch_bounds__(256) void gates1_gemm(const float* __restrict__ w_ih1)
{
    __shared__ float a_s[32][36];
    __shared__ float w_s[128][33];
    const int r0 = blockIdx.x * 32, j0 = blockIdx.y * 32, dir = blockIdx.z;
    const float* w = w_ih1 + (long)dir * G_ * 1024;
    float acc[4][4] = {};
    seg_accum<32>(a_s, w_s, &g_h0seq[0][0][0][0], H_, 0, w,       1024, H_, r0, j0, acc);
    seg_accum<32>(a_s, w_s, &g_h0seq[1][0][0][0], H_, 0, w + 512, 1024, H_, r0, j0, acc);
    const int tx = threadIdx.x & 31, ty = threadIdx.x >> 5;
    float* op = &g_gates1[dir][0][0][0];
    #pragma unroll
    for (int gi = 0; gi < 4; ++gi)
        #pragma unroll
        for (int bi = 0; bi < 4; ++bi)
            op[(long)(r0 + ty * 4 + bi) * G_ + j0 + gi * 512 + tx] = acc[bi][gi];
}

// ---------------- encoder layer 1: persistent, 512 steps, both dirs --------
__global__ __launch_bounds__(256, 1) void enc_l1_persist(
    const float* __restrict__ w_hh, const float* __restrict__ bias)
{
    __shared__ float a_s[32][36];
    __shared__ float w_s[128][33];
    const int bid = blockIdx.x;
    const int dir = bid >> 6, rr = bid & 63;
    const int b0 = (rr >> 4) * 32, j0 = (rr & 15) * 32;
    const int tx = threadIdx.x & 31, ty = threadIdx.x >> 5;
    const int j = j0 + tx;
    const float* bs = bias + dir * G_;
    const float bI = __ldg(bs + j),        bF = __ldg(bs + 512 + j),
                bG = __ldg(bs + 1024 + j), bO = __ldg(bs + 1536 + j);
    const float* whh = w_hh + (long)dir * G_ * H_;
    float cacc[4] = {0.f, 0.f, 0.f, 0.f};

    for (int s = 0; s < T_; ++s) {
        const int t = dir ? (T_ - 1 - s) : s;
        float acc[4][4] = {};
        if (s > 0)
            seg_accum<32>(a_s, w_s, &g_h1buf[s & 1][dir][0][0], H_, 1, whh, H_, H_, b0, j0, acc);
        const float* gp = &g_gates1[dir][t][0][0];
        #pragma unroll
        for (int bi = 0; bi < 4; ++bi) {
            const int b = b0 + ty * 4 + bi;
            const float* gr = gp + (long)b * G_;
            float i_ = sigm_(acc[bi][0] + __ldg(gr + j)        + bI);
            float f_ = sigm_(acc[bi][1] + __ldg(gr + 512 + j)  + bF);
            float g_ = tanh_(acc[bi][2] + __ldg(gr + 1024 + j) + bG);
            float o_ = sigm_(acc[bi][3] + __ldg(gr + 1536 + j) + bO);
            float c  = f_ * cacc[bi] + i_ * g_;
            cacc[bi] = c;
            g_h1buf[(s + 1) & 1][dir][b][j] = o_ * tanh_(c);
        }
        grid_barrier();
    }
    #pragma unroll
    for (int bi = 0; bi < 4; ++bi)
        g_c[1][dir][b0 + ty * 4 + bi][j] = cacc[bi];
}

// ---------------- bridge: elu(h/c_flat @ Wbᵀ + bb) -> decoder init ---------
__global__ __launch_bounds__(256) void bridge_kernel(
    const float* __restrict__ wb, const float* __restrict__ bb)
{
    __shared__ float in_s[32][33], w_s2[32][33];
    const int tid = threadIdx.x, tx = tid & 31, ty = tid >> 5;
    const int b0 = blockIdx.x * 32, m0 = blockIdx.y * 32, z = blockIdx.z;
    const float* srcs[4];
    if (z == 0) {
        srcs[0] = &g_h0seq[0][T_ - 1][0][0]; srcs[1] = &g_h0seq[1][0][0][0];
        srcs[2] = &g_h1buf[0][0][0][0];      srcs[3] = &g_h1buf[0][1][0][0];
    } else {
        srcs[0] = &g_c[0][0][0][0]; srcs[1] = &g_c[0][1][0][0];
        srcs[2] = &g_c[1][0][0][0]; srcs[3] = &g_c[1][1][0][0];
    }
    float acc[4] = {0.f, 0.f, 0.f, 0.f};
    for (int k0 = 0; k0 < 2048; k0 += 32) {
        __syncthreads();
        const float* src = srcs[k0 >> 9];
        const int kl = k0 & 511;
        #pragma unroll
        for (int i = 0; i < 4; ++i) {
            int e = tid + i * 256;
            int r = e >> 5, kk = e & 31;
            in_s[r][kk] = src[(long)(b0 + r) * H_ + kl + kk];
            w_s2[r][kk] = wb[(long)(m0 + r) * 2048 + k0 + kk];
        }
        __syncthreads();
        #pragma unroll
        for (int kk = 0; kk < 32; ++kk) {
            float wv = w_s2[tx][kk];
            #pragma unroll
            for (int bi = 0; bi < 4; ++bi)
                acc[bi] = fmaf(in_s[ty * 4 + bi][kk], wv, acc[bi]);
        }
    }
    const int m = m0 + tx;
    #pragma unroll
    for (int bi = 0; bi < 4; ++bi) {
        int b = b0 + ty * 4 + bi;
        float v = acc[bi] + bb[m];
        v = (v > 0.f) ? v : expm1f(v);
        if (z == 0) {
            if (m < 512) g_dec_h0[0][b][m] = v; else g_dec_h1[0][b][m - 512] = v;
        } else {
            if (m < 512) g_dec_c0[b][m] = v;    else g_dec_c1[b][m - 512] = v;
        }
    }
}

// ---------------- decoder: persistent, 64 steps (cell0, cell1, proj) -------
__global__ __launch_bounds__(256, 1) void dec_persist(
    const float* __restrict__ X, const float* __restrict__ fut,
    const float* __restrict__ dwih0, const float* __restrict__ dwhh0,
    const float* __restrict__ db0,
    const float* __restrict__ dwih1, const float* __restrict__ dwhh1,
    const float* __restrict__ db1,
    const float* __restrict__ wo, const float* __restrict__ bo,
    float* __restrict__ out)
{
    __shared__ float a_s[32][20];
    __shared__ float w_s[128][33];
    __shared__ float red[8][MQ_];
    const int bid = blockIdx.x, tid = threadIdx.x;
    const int tx = tid & 31, ty = tid >> 5;
    const int b0 = (bid >> 4) * 16, j0 = (bid & 15) * 32;
    const int j = j0 + tx;

    // init decoder input x = [y0 = X[:, -1, 0], fut[:,0,:]]
    if (tid < DIN_)
        g_decx[bid][tid] = (tid == 0)
            ? __ldg(X + (long)bid * T_ * DIN_ + (T_ - 1) * DIN_)
            : __ldg(fut + (long)bid * HOR_ * DFF_ + (tid - 1));

    const float b0I = __ldg(db0 + j),        b0F = __ldg(db0 + 512 + j),
                b0G = __ldg(db0 + 1024 + j), b0O = __ldg(db0 + 1536 + j);
    const float b1I = __ldg(db1 + j),        b1F = __ldg(db1 + 512 + j),
                b1G = __ldg(db1 + 1024 + j), b1O = __ldg(db1 + 1536 + j);
    float c0[2], c1[2];
    #pragma unroll
    for (int bi = 0; bi < 2; ++bi) {
        c0[bi] = g_dec_c0[b0 + ty * 2 + bi][j];
        c1[bi] = g_dec_c1[b0 + ty * 2 + bi][j];
    }
    grid_barrier();

    for (int s = 0; s < HOR_; ++s) {
        // ---- cell 0 ----
        {
            float acc[2][4] = {};
            seg_accum<16>(a_s, w_s, &g_decx[0][0], DIN_, 1, dwih0, DIN_, DIN_, b0, j0, acc);
            seg_accum<16>(a_s, w_s, &g_dec_h0[s & 1][0][0], H_, 1, dwhh0, H_, H_, b0, j0, acc);
            #pragma unroll
            for (int bi = 0; bi < 2; ++bi) {
                float i_ = sigm_(acc[bi][0] + b0I);
                float f_ = sigm_(acc[bi][1] + b0F);
                float g_ = tanh_(acc[bi][2] + b0G);
                float o_ = sigm_(acc[bi][3] + b0O);
                float c  = f_ * c0[bi] + i_ * g_;
                c0[bi] = c;
                g_dec_h0[(s + 1) & 1][b0 + ty * 2 + bi][j] = o_ * tanh_(c);
            }
        }
        grid_barrier();
        // ---- cell 1 ----
        {
            float acc[2][4] = {};
            seg_accum<16>(a_s, w_s, &g_dec_h0[(s + 1) & 1][0][0], H_, 1, dwih1, H_, H_, b0, j0, acc);
            seg_accum<16>(a_s, w_s, &g_dec_h1[s & 1][0][0],       H_, 1, dwhh1, H_, H_, b0, j0, acc);
            #pragma unroll
            for (int bi = 0; bi < 2; ++bi) {
                float i_ = sigm_(acc[bi][0] + b1I);
                float f_ = sigm_(acc[bi][1] + b1F);
                float g_ = tanh_(acc[bi][2] + b1G);
                float o_ = sigm_(acc[bi][3] + b1O);
                float c  = f_ * c1[bi] + i_ * g_;
                c1[bi] = c;
                g_dec_h1[(s + 1) & 1][b0 + ty * 2 + bi][j] = o_ * tanh_(c);
            }
        }
        grid_barrier();
        // ---- output projection + feedback (block = batch row) ----
        {
            const float* h1 = &g_dec_h1[(s + 1) & 1][bid][0];
            float part[MQ_] = {0.f, 0.f, 0.f, 0.f, 0.f};
            for (int k = tid; k < H_; k += 256) {
                float hv = __ldcg(h1 + k);
                #pragma unroll
                for (int q = 0; q < MQ_; ++q)
                    part[q] = fmaf(hv, __ldg(wo + q * H_ + k), part[q]);
            }
            #pragma unroll
            for (int o = 16; o; o >>= 1)
                #pragma unroll
                for (int q = 0; q < MQ_; ++q)
                    part[q] += __shfl_down_sync(0xffffffffu, part[q], o);
            if ((tid & 31) == 0)
                #pragma unroll
                for (int q = 0; q < MQ_; ++q) red[tid >> 5][q] = part[q];
            __syncthreads();
            if (tid < MQ_) {
                float v = __ldg(bo + tid);
                #pragma unroll
                for (int w2 = 0; w2 < 8; ++w2) v += red[w2][tid];
                out[(long)bid * HOR_ * MQ_ + s * MQ_ + tid] = v;
                if (tid == 0) g_decx[bid][0] = v;
            }
            if (s + 1 < HOR_ && tid >= 32 && tid < 32 + DFF_)
                g_decx[bid][tid - 31] =
                    __ldg(fut + (long)bid * HOR_ * DFF_ + (s + 1) * DFF_ + (tid - 32));
        }
        grid_barrier();
    }
}

// ---------------- launcher (5 graph nodes) ----------------
extern "C" void kernel_launch(void* const* d_in, const int* in_sizes, int n_in,
                              void* d_out, int out_size)
{
    int off = (n_in >= 4 && in_sizes[3] == 1) ? 0 : -1;
    const float* X     = (const float*)d_in[0];
    const float* fut   = (const float*)d_in[1];
    const float* ewih0 = (const float*)d_in[4 + off];
    const float* ewhh0 = (const float*)d_in[5 + off];
    const float* eb0   = (const float*)d_in[6 + off];
    const float* ewih1 = (const float*)d_in[7 + off];
    const float* ewhh1 = (const float*)d_in[8 + off];
    const float* eb1   = (const float*)d_in[9 + off];
    const float* dwih0 = (const float*)d_in[10 + off];
    const float* dwhh0 = (const float*)d_in[11 + off];
    const float* db0   = (const float*)d_in[12 + off];
    const float* dwih1 = (const float*)d_in[13 + off];
    const float* dwhh1 = (const float*)d_in[14 + off];
    const float* db1   = (const float*)d_in[15 + off];
    const float* wb    = (const float*)d_in[16 + off];
    const float* bb    = (const float*)d_in[17 + off];
    const float* wo    = (const float*)d_in[18 + off];
    const float* bo    = (const float*)d_in[19 + off];
    float* out = (float*)d_out;

    enc_l0_persist<<<NBLK, 256>>>(X, ewih0, ewhh0, eb0);
    gates1_gemm<<<dim3(2048, 16, 2), 256>>>(ewih1);
    enc_l1_persist<<<NBLK, 256>>>(ewhh1, eb1);
    bridge_kernel<<<dim3(4, 32, 2), 256>>>(wb, bb);
    dec_persist<<<NBLK, 256>>>(X, fut, dwih0, dwhh0, db0,
                               dwih1, dwhh1, db1, wo, bo, out);
}